// round 7
// baseline (speedup 1.0000x reference)
#include <cuda_runtime.h>
#include <cuda_bf16.h>
#include <cstdint>

#define NROWS 8192
#define DDIM  1024

#define MT 128
#define NT 128
#define KT 64                       // bf16 per K chunk
#define STR 72                      // smem row stride in bf16 (144B; conflict-free ldmatrix)
#define ROWB (STR * 2)              // 144 bytes
#define NSTAGE 3
#define KCHUNKS (DDIM / KT)         // 16
#define NBLK (NROWS / MT)           // 64
#define NTILES (NBLK * (NBLK + 1) / 2)   // 2080
#define GRID 148

#define ASTAGE_B (MT * ROWB)              // 18432
#define STAGE_B  (2 * ASTAGE_B)           // 36864
#define PIPE_B   (NSTAGE * STAGE_B)       // 110592
#define MERGE_W  20
#define ROWM_OFF PIPE_B                   // rowm[128][20] f32 = 10240
#define COLM_OFF (PIPE_B + 10240)         // colm[128][20] f32 = 10240
#define SMEM_DYN (PIPE_B + 20480)         // 131072

__device__ __align__(16) __nv_bfloat16 g_xb[(size_t)NROWS * DDIM];
__device__ float g_sq[NROWS];
__device__ float g_cand[NBLK][NROWS][5];   // slot = other block index

__device__ __forceinline__ void ins5(float t[5], float v) {
    if (v < t[4]) {
        t[4] = v;
        if (t[4] < t[3]) { float x = t[3]; t[3] = t[4]; t[4] = x;
        if (t[3] < t[2]) { float x = t[2]; t[2] = t[3]; t[3] = x;
        if (t[2] < t[1]) { float x = t[1]; t[1] = t[2]; t[2] = x;
        if (t[1] < t[0]) { float x = t[0]; t[0] = t[1]; t[1] = x; } } } }
    }
}

__device__ __forceinline__ void cp_async16(uint32_t dst, const void* src) {
    asm volatile("cp.async.cg.shared.global [%0], [%1], 16;" :: "r"(dst), "l"(src));
}
__device__ __forceinline__ void ldm4(uint32_t r[4], uint32_t addr) {
    asm volatile("ldmatrix.sync.aligned.m8n8.x4.shared.b16 {%0,%1,%2,%3}, [%4];"
                 : "=r"(r[0]), "=r"(r[1]), "=r"(r[2]), "=r"(r[3]) : "r"(addr));
}
__device__ __forceinline__ void mma16816(float c[4], const uint32_t a[4],
                                         uint32_t b0, uint32_t b1) {
    asm volatile(
        "mma.sync.aligned.m16n8k16.row.col.f32.bf16.bf16.f32 "
        "{%0,%1,%2,%3}, {%4,%5,%6,%7}, {%8,%9}, {%0,%1,%2,%3};\n"
        : "+f"(c[0]), "+f"(c[1]), "+f"(c[2]), "+f"(c[3])
        : "r"(a[0]), "r"(a[1]), "r"(a[2]), "r"(a[3]), "r"(b0), "r"(b1));
}

__device__ __forceinline__ void decode_tile(int t, int& bi, int& bj) {
    int rem = t, i = 0;
    while (rem >= NBLK - i) { rem -= NBLK - i; i++; }
    bi = i; bj = i + rem;
}

// ---------------------------------------------------------------------------
// Kernel A: bf16 convert + squared norms
// ---------------------------------------------------------------------------
__global__ __launch_bounds__(256) void prep_kernel(const float* __restrict__ xr) {
    int row = blockIdx.x;
    int tid = threadIdx.x;
    float4 v = reinterpret_cast<const float4*>(xr + (size_t)row * DDIM)[tid];
    __nv_bfloat162 h0 = __floats2bfloat162_rn(v.x, v.y);
    __nv_bfloat162 h1 = __floats2bfloat162_rn(v.z, v.w);
    uint2 pk;
    pk.x = *reinterpret_cast<uint32_t*>(&h0);
    pk.y = *reinterpret_cast<uint32_t*>(&h1);
    reinterpret_cast<uint2*>(g_xb + (size_t)row * DDIM)[tid] = pk;

    float s = v.x * v.x + v.y * v.y + v.z * v.z + v.w * v.w;
    #pragma unroll
    for (int o = 16; o; o >>= 1) s += __shfl_xor_sync(0xffffffffu, s, o);
    __shared__ float red[8];
    if ((tid & 31) == 0) red[tid >> 5] = s;
    __syncthreads();
    if (tid == 0) {
        float tot = 0.f;
        #pragma unroll
        for (int i = 0; i < 8; i++) tot += red[i];
        g_sq[row] = tot;
    }
}

// ---------------------------------------------------------------------------
// Kernel B: persistent symmetric Gram; continuous cross-tile cp.async pipeline.
// ---------------------------------------------------------------------------
__global__ __launch_bounds__(512, 1) void gram_kernel() {
    extern __shared__ __align__(16) unsigned char sm[];
    const uint32_t st0 = (uint32_t)__cvta_generic_to_shared(sm);
    float (*rowm)[MERGE_W] = reinterpret_cast<float (*)[MERGE_W]>(sm + ROWM_OFF);
    float (*colm)[MERGE_W] = reinterpret_cast<float (*)[MERGE_W]>(sm + COLM_OFF);

    const int tid = threadIdx.x;
    const int wid = tid >> 5, lane = tid & 31;
    const int warp_m = wid >> 2, warp_n = wid & 3;
    const int r = lane >> 2, qq = lane & 3;

    const int myTiles = (NTILES - (int)blockIdx.x + GRID - 1) / GRID;
    const int totalIt = myTiles * KCHUNKS;

    // per-thread load-unit geometry
    const int ur0 = tid >> 3, uq0 = tid & 7;
    const uint32_t dA0 = ur0 * ROWB + uq0 * 16;
    const uint32_t dA1 = (ur0 + 64) * ROWB + uq0 * 16;

    // prefetch cursor
    int pTile = blockIdx.x, pBi, pBj;
    decode_tile(pTile, pBi, pBj);
    const __nv_bfloat16* aP0 = g_xb + (size_t)(pBi * MT + ur0) * DDIM + uq0 * 8;
    const __nv_bfloat16* bP0 = g_xb + (size_t)(pBj * NT + ur0) * DDIM + uq0 * 8;
    // compute cursor
    int cTile = pTile, cBi = pBi, cBj = pBj;

    const uint32_t aFragOff = (uint32_t)((warp_m * 32 + (lane & 15)) * ROWB + (lane >> 4) * 16);
    const uint32_t bFragOff = (uint32_t)(ASTAGE_B + (warp_n * 32 + (lane & 15)) * ROWB + (lane >> 4) * 16);

    float acc[2][4][4];
    #pragma unroll
    for (int mb = 0; mb < 2; mb++)
        #pragma unroll
        for (int nb = 0; nb < 4; nb++)
            #pragma unroll
            for (int e = 0; e < 4; e++) acc[mb][nb][e] = 0.f;

    float t5[4][5];
    #pragma unroll
    for (int a = 0; a < 4; a++)
        #pragma unroll
        for (int s = 0; s < 5; s++) t5[a][s] = 3.0e38f;

    auto issue = [&](int kc, int slot) {
        const size_t koff = (size_t)kc * KT;
        const uint32_t sb = st0 + slot * STAGE_B;
        cp_async16(sb + dA0, aP0 + koff);
        cp_async16(sb + dA1, aP0 + (size_t)64 * DDIM + koff);
        cp_async16(sb + ASTAGE_B + dA0, bP0 + koff);
        cp_async16(sb + ASTAGE_B + dA1, bP0 + (size_t)64 * DDIM + koff);
        asm volatile("cp.async.commit_group;" ::: "memory");
    };

    issue(0, 0);
    issue(1, 1);

    #pragma unroll 1
    for (int g = 0; g < totalIt; g++) {
        if (g < totalIt - 1) asm volatile("cp.async.wait_group 1;" ::: "memory");
        else                 asm volatile("cp.async.wait_group 0;" ::: "memory");
        __syncthreads();
        const int g2 = g + 2;
        if (g2 < totalIt) {
            if ((g2 & (KCHUNKS - 1)) < 2 && (g2 >> 4) != (pTile - (int)blockIdx.x) / GRID) {
                pTile += GRID;
                decode_tile(pTile, pBi, pBj);
                aP0 = g_xb + (size_t)(pBi * MT + ur0) * DDIM + uq0 * 8;
                bP0 = g_xb + (size_t)(pBj * NT + ur0) * DDIM + uq0 * 8;
            }
            issue(g2 & (KCHUNKS - 1), g2 % NSTAGE);
        }

        const uint32_t sb = st0 + (g % NSTAGE) * STAGE_B;
        const uint32_t aB = sb + aFragOff;
        const uint32_t bB = sb + bFragOff;

        #pragma unroll
        for (int ks = 0; ks < 4; ks++) {
            uint32_t a0[4], a1[4], b0[4], b1[4];
            ldm4(a0, aB + ks * 32);
            ldm4(a1, aB + 16 * ROWB + ks * 32);
            ldm4(b0, bB + ks * 32);
            ldm4(b1, bB + 16 * ROWB + ks * 32);
            mma16816(acc[0][0], a0, b0[0], b0[2]);
            mma16816(acc[1][0], a1, b0[0], b0[2]);
            mma16816(acc[0][1], a0, b0[1], b0[3]);
            mma16816(acc[1][1], a1, b0[1], b0[3]);
            mma16816(acc[0][2], a0, b1[0], b1[2]);
            mma16816(acc[1][2], a1, b1[0], b1[2]);
            mma16816(acc[0][3], a0, b1[1], b1[3]);
            mma16816(acc[1][3], a1, b1[1], b1[3]);
        }

        if ((g & (KCHUNKS - 1)) == (KCHUNKS - 1)) {
            // ---------------- per-tile epilogue ----------------
            const int i0 = cBi * MT, j0 = cBj * NT;
            float sqi[4];
            #pragma unroll
            for (int a = 0; a < 4; a++)
                sqi[a] = __ldg(&g_sq[i0 + warp_m * 32 + (a >> 1) * 16 + (a & 1) * 8 + r]);

            #pragma unroll
            for (int nb = 0; nb < 4; nb++)
                #pragma unroll
                for (int c = 0; c < 2; c++) {
                    const int cl = warp_n * 32 + nb * 8 + qq * 2 + c;
                    const int gj = j0 + cl;
                    const float sqj = __ldg(&g_sq[gj]);
                    float tc[5] = {3e38f, 3e38f, 3e38f, 3e38f, 3e38f};
                    #pragma unroll
                    for (int a = 0; a < 4; a++) {
                        const int mb = a >> 1, h = a & 1;
                        const int gi = i0 + warp_m * 32 + mb * 16 + h * 8 + r;
                        float d2 = sqi[a] + sqj - 2.0f * acc[mb][nb][h * 2 + c];
                        d2 = fmaxf(d2, 0.0f);
                        if (gj != gi) { ins5(t5[a], d2); ins5(tc, d2); }
                        acc[mb][nb][h * 2 + c] = 0.f;
                    }
                    // column reduce across r-lanes (stride-4 butterfly)
                    #pragma unroll
                    for (int m = 4; m <= 16; m <<= 1)
                        #pragma unroll
                        for (int s = 0; s < 5; s++)
                            ins5(tc, __shfl_xor_sync(0xffffffffu, tc[s], m));
                    if (r == 0) {
                        #pragma unroll
                        for (int s = 0; s < 5; s++) colm[cl][warp_m * 5 + s] = tc[s];
                    }
                }

            // row reduce across qq-lanes
            #pragma unroll
            for (int a = 0; a < 4; a++) {
                #pragma unroll
                for (int m = 1; m <= 2; m <<= 1)
                    #pragma unroll
                    for (int s = 0; s < 5; s++)
                        ins5(t5[a], __shfl_xor_sync(0xffffffffu, t5[a][s], m));
                if (qq == 0) {
                    const int rl = warp_m * 32 + (a >> 1) * 16 + (a & 1) * 8 + r;
                    #pragma unroll
                    for (int s = 0; s < 5; s++) rowm[rl][warp_n * 5 + s] = t5[a][s];
                }
                #pragma unroll
                for (int s = 0; s < 5; s++) t5[a][s] = 3.0e38f;
            }
            __syncthreads();

            if (tid < MT) {
                float t[5] = {3e38f, 3e38f, 3e38f, 3e38f, 3e38f};
                #pragma unroll
                for (int k = 0; k < 20; k++) ins5(t, rowm[tid][k]);
                #pragma unroll
                for (int s = 0; s < 5; s++) g_cand[cBj][i0 + tid][s] = t[s];
            } else if (tid < 256 && cBi != cBj) {
                const int cl = tid - 128;
                float t[5] = {3e38f, 3e38f, 3e38f, 3e38f, 3e38f};
                #pragma unroll
                for (int k = 0; k < 20; k++) ins5(t, colm[cl][k]);
                #pragma unroll
                for (int s = 0; s < 5; s++) g_cand[cBi][j0 + cl][s] = t[s];
            }

            cTile += GRID;
            if (cTile < NTILES) decode_tile(cTile, cBi, cBj);
        }
    }
}

// ---------------------------------------------------------------------------
// Kernel C: merge 64 candidate slots -> score -> weight -> scale into out[2,...]
// ---------------------------------------------------------------------------
__global__ __launch_bounds__(256) void finalize_kernel(const float* __restrict__ xr,
                                                       const float* __restrict__ xi,
                                                       float* __restrict__ out) {
    const int row = blockIdx.x;
    const int tid = threadIdx.x;
    __shared__ float buf[40];
    __shared__ float wsh;
    if (tid < 8) {
        float t[5] = {3e38f, 3e38f, 3e38f, 3e38f, 3e38f};
        #pragma unroll
        for (int s8 = 0; s8 < 8; s8++) {
            const int slot = tid * 8 + s8;
            #pragma unroll
            for (int s = 0; s < 5; s++) ins5(t, g_cand[slot][row][s]);
        }
        #pragma unroll
        for (int s = 0; s < 5; s++) buf[tid * 5 + s] = t[s];
    }
    __syncthreads();
    if (tid == 0) {
        float t[5] = {3e38f, 3e38f, 3e38f, 3e38f, 3e38f};
        #pragma unroll
        for (int k = 0; k < 40; k++) ins5(t, buf[k]);
        float sc = (sqrtf(t[0]) + sqrtf(t[1]) + sqrtf(t[2]) + sqrtf(t[3]) + sqrtf(t[4])) * 0.2f;
        wsh = (sc > 0.1f) ? expf(-sc * (1.0f / 32.0f)) : 0.0f;
    }
    __syncthreads();
    const float w = wsh;
    float4 a = reinterpret_cast<const float4*>(xr + (size_t)row * DDIM)[tid];
    float4 b = reinterpret_cast<const float4*>(xi + (size_t)row * DDIM)[tid];
    a.x *= w; a.y *= w; a.z *= w; a.w *= w;
    b.x *= w; b.y *= w; b.z *= w; b.w *= w;
    reinterpret_cast<float4*>(out + (size_t)row * DDIM)[tid] = a;
    reinterpret_cast<float4*>(out + ((size_t)NROWS + row) * DDIM)[tid] = b;
}

// ---------------------------------------------------------------------------
extern "C" void kernel_launch(void* const* d_in, const int* in_sizes, int n_in,
                              void* d_out, int out_size) {
    const float* xr = (const float*)d_in[0];
    const float* xi = (const float*)d_in[1];
    float* out = (float*)d_out;

    cudaFuncSetAttribute(gram_kernel, cudaFuncAttributeMaxDynamicSharedMemorySize, SMEM_DYN);

    prep_kernel<<<NROWS, 256>>>(xr);
    gram_kernel<<<GRID, 512, SMEM_DYN>>>();
    finalize_kernel<<<NROWS, 256>>>(xr, xi, out);
}

// round 8
// speedup vs baseline: 1.0068x; 1.0068x over previous
#include <cuda_runtime.h>
#include <cuda_bf16.h>
#include <cstdint>

#define NROWS 8192
#define DDIM  1024

#define MT 128
#define NT 128
#define KT 64                       // bf16 per K chunk
#define STR 72                      // smem row stride in bf16 (144B; conflict-free ldmatrix)
#define ROWB (STR * 2)              // 144 bytes
#define NSTAGE 3
#define KCHUNKS (DDIM / KT)         // 16
#define NBLK (NROWS / MT)           // 64
#define NTILES (NBLK * (NBLK + 1) / 2)   // 2080
#define GRID 148

#define ASTAGE_B (MT * ROWB)              // 18432
#define STAGE_B  (2 * ASTAGE_B)           // 36864
#define PIPE_B   (NSTAGE * STAGE_B)       // 110592
#define MERGE_W  20
#define ROWM_OFF PIPE_B                   // rowm[128][20] f32 = 10240
#define COLM_OFF (PIPE_B + 10240)         // colm[128][20] f32 = 10240
#define SMEM_DYN (PIPE_B + 20480)         // 131072

__device__ __align__(16) __nv_bfloat16 g_xb[(size_t)NROWS * DDIM];
__device__ float g_sq[NROWS];
__device__ float g_cand[NBLK][NROWS][5];   // slot = other block index

__device__ __forceinline__ void ins5(float t[5], float v) {
    if (v < t[4]) {
        t[4] = v;
        if (t[4] < t[3]) { float x = t[3]; t[3] = t[4]; t[4] = x;
        if (t[3] < t[2]) { float x = t[2]; t[2] = t[3]; t[3] = x;
        if (t[2] < t[1]) { float x = t[1]; t[1] = t[2]; t[2] = x;
        if (t[1] < t[0]) { float x = t[0]; t[0] = t[1]; t[1] = x; } } } }
    }
}

// exact top-5 butterfly exchange: snapshot partner's list BEFORE inserting
__device__ __forceinline__ void merge5_xor(float t[5], int m) {
    float o[5];
    #pragma unroll
    for (int s = 0; s < 5; s++) o[s] = __shfl_xor_sync(0xffffffffu, t[s], m);
    #pragma unroll
    for (int s = 0; s < 5; s++) ins5(t, o[s]);
}

__device__ __forceinline__ void cp_async16(uint32_t dst, const void* src) {
    asm volatile("cp.async.cg.shared.global [%0], [%1], 16;" :: "r"(dst), "l"(src));
}
__device__ __forceinline__ void ldm4(uint32_t r[4], uint32_t addr) {
    asm volatile("ldmatrix.sync.aligned.m8n8.x4.shared.b16 {%0,%1,%2,%3}, [%4];"
                 : "=r"(r[0]), "=r"(r[1]), "=r"(r[2]), "=r"(r[3]) : "r"(addr));
}
__device__ __forceinline__ void mma16816(float c[4], const uint32_t a[4],
                                         uint32_t b0, uint32_t b1) {
    asm volatile(
        "mma.sync.aligned.m16n8k16.row.col.f32.bf16.bf16.f32 "
        "{%0,%1,%2,%3}, {%4,%5,%6,%7}, {%8,%9}, {%0,%1,%2,%3};\n"
        : "+f"(c[0]), "+f"(c[1]), "+f"(c[2]), "+f"(c[3])
        : "r"(a[0]), "r"(a[1]), "r"(a[2]), "r"(a[3]), "r"(b0), "r"(b1));
}

__device__ __forceinline__ void decode_tile(int t, int& bi, int& bj) {
    int rem = t, i = 0;
    while (rem >= NBLK - i) { rem -= NBLK - i; i++; }
    bi = i; bj = i + rem;
}

// ---------------------------------------------------------------------------
// Kernel A: bf16 convert + squared norms
// ---------------------------------------------------------------------------
__global__ __launch_bounds__(256) void prep_kernel(const float* __restrict__ xr) {
    int row = blockIdx.x;
    int tid = threadIdx.x;
    float4 v = reinterpret_cast<const float4*>(xr + (size_t)row * DDIM)[tid];
    __nv_bfloat162 h0 = __floats2bfloat162_rn(v.x, v.y);
    __nv_bfloat162 h1 = __floats2bfloat162_rn(v.z, v.w);
    uint2 pk;
    pk.x = *reinterpret_cast<uint32_t*>(&h0);
    pk.y = *reinterpret_cast<uint32_t*>(&h1);
    reinterpret_cast<uint2*>(g_xb + (size_t)row * DDIM)[tid] = pk;

    float s = v.x * v.x + v.y * v.y + v.z * v.z + v.w * v.w;
    #pragma unroll
    for (int o = 16; o; o >>= 1) s += __shfl_xor_sync(0xffffffffu, s, o);
    __shared__ float red[8];
    if ((tid & 31) == 0) red[tid >> 5] = s;
    __syncthreads();
    if (tid == 0) {
        float tot = 0.f;
        #pragma unroll
        for (int i = 0; i < 8; i++) tot += red[i];
        g_sq[row] = tot;
    }
}

// ---------------------------------------------------------------------------
// Kernel B: persistent symmetric Gram; division-free cross-tile pipeline.
// ---------------------------------------------------------------------------
__global__ __launch_bounds__(512, 1) void gram_kernel() {
    extern __shared__ __align__(16) unsigned char sm[];
    const uint32_t st0 = (uint32_t)__cvta_generic_to_shared(sm);
    float (*rowm)[MERGE_W] = reinterpret_cast<float (*)[MERGE_W]>(sm + ROWM_OFF);
    float (*colm)[MERGE_W] = reinterpret_cast<float (*)[MERGE_W]>(sm + COLM_OFF);

    const int tid = threadIdx.x;
    const int wid = tid >> 5, lane = tid & 31;
    const int warp_m = wid >> 2, warp_n = wid & 3;
    const int r = lane >> 2, qq = lane & 3;

    const int myTiles = (NTILES - (int)blockIdx.x + GRID - 1) / GRID;
    const int totalIt = myTiles * KCHUNKS;

    const int ur0 = tid >> 3, uq0 = tid & 7;
    const uint32_t dA0 = ur0 * ROWB + uq0 * 16;
    const uint32_t dA1 = (ur0 + 64) * ROWB + uq0 * 16;

    const uint32_t aFragOff = (uint32_t)((warp_m * 32 + (lane & 15)) * ROWB + (lane >> 4) * 16);
    const uint32_t bFragOff = (uint32_t)(ASTAGE_B + (warp_n * 32 + (lane & 15)) * ROWB + (lane >> 4) * 16);

    float acc[2][4][4];
    #pragma unroll
    for (int mb = 0; mb < 2; mb++)
        #pragma unroll
        for (int nb = 0; nb < 4; nb++)
            #pragma unroll
            for (int e = 0; e < 4; e++) acc[mb][nb][e] = 0.f;

    float t5[4][5];
    #pragma unroll
    for (int a = 0; a < 4; a++)
        #pragma unroll
        for (int s = 0; s < 5; s++) t5[a][s] = 3.0e38f;

    auto issue = [&](const __nv_bfloat16* aP, const __nv_bfloat16* bP,
                     int kc, int slot) {
        const size_t koff = (size_t)kc * KT;
        const uint32_t sb = st0 + slot * STAGE_B;
        cp_async16(sb + dA0, aP + koff);
        cp_async16(sb + dA1, aP + (size_t)64 * DDIM + koff);
        cp_async16(sb + ASTAGE_B + dA0, bP + koff);
        cp_async16(sb + ASTAGE_B + dA1, bP + (size_t)64 * DDIM + koff);
        asm volatile("cp.async.commit_group;" ::: "memory");
    };

    int tile = blockIdx.x, bi, bj;
    decode_tile(tile, bi, bj);
    const __nv_bfloat16* curA = g_xb + (size_t)(bi * MT + ur0) * DDIM + uq0 * 8;
    const __nv_bfloat16* curB = g_xb + (size_t)(bj * NT + ur0) * DDIM + uq0 * 8;

    issue(curA, curB, 0, 0);
    issue(curA, curB, 1, 1);

    int slotI = 2, slotC = 0, g = 0;

    #pragma unroll 1
    for (int w = 0; w < myTiles; w++) {
        // next-tile pointers (decoded once per tile; dummy = current for last tile)
        int nBi = bi, nBj = bj;
        if (w + 1 < myTiles) decode_tile(tile + GRID, nBi, nBj);
        const __nv_bfloat16* nxtA = g_xb + (size_t)(nBi * MT + ur0) * DDIM + uq0 * 8;
        const __nv_bfloat16* nxtB = g_xb + (size_t)(nBj * NT + ur0) * DDIM + uq0 * 8;

        #pragma unroll 1
        for (int kc = 0; kc < KCHUNKS; kc++, g++) {
            if (g < totalIt - 1) asm volatile("cp.async.wait_group 1;" ::: "memory");
            else                 asm volatile("cp.async.wait_group 0;" ::: "memory");
            __syncthreads();
            if (g + 2 < totalIt) {
                if (kc < KCHUNKS - 2) issue(curA, curB, kc + 2, slotI);
                else                  issue(nxtA, nxtB, kc - (KCHUNKS - 2), slotI);
                if (++slotI == NSTAGE) slotI = 0;
            }

            const uint32_t sb = st0 + slotC * STAGE_B;
            if (++slotC == NSTAGE) slotC = 0;
            const uint32_t aB = sb + aFragOff;
            const uint32_t bB = sb + bFragOff;

            #pragma unroll
            for (int ks = 0; ks < 4; ks++) {
                uint32_t a0[4], a1[4], b0[4], b1[4];
                ldm4(a0, aB + ks * 32);
                ldm4(a1, aB + 16 * ROWB + ks * 32);
                ldm4(b0, bB + ks * 32);
                ldm4(b1, bB + 16 * ROWB + ks * 32);
                mma16816(acc[0][0], a0, b0[0], b0[2]);
                mma16816(acc[1][0], a1, b0[0], b0[2]);
                mma16816(acc[0][1], a0, b0[1], b0[3]);
                mma16816(acc[1][1], a1, b0[1], b0[3]);
                mma16816(acc[0][2], a0, b1[0], b1[2]);
                mma16816(acc[1][2], a1, b1[0], b1[2]);
                mma16816(acc[0][3], a0, b1[1], b1[3]);
                mma16816(acc[1][3], a1, b1[1], b1[3]);
            }
        }

        // ---------------- per-tile epilogue ----------------
        {
            const int i0 = bi * MT, j0 = bj * NT;
            float sqi[4];
            #pragma unroll
            for (int a = 0; a < 4; a++)
                sqi[a] = __ldg(&g_sq[i0 + warp_m * 32 + (a >> 1) * 16 + (a & 1) * 8 + r]);

            #pragma unroll
            for (int nb = 0; nb < 4; nb++)
                #pragma unroll
                for (int c = 0; c < 2; c++) {
                    const int cl = warp_n * 32 + nb * 8 + qq * 2 + c;
                    const int gj = j0 + cl;
                    const float sqj = __ldg(&g_sq[gj]);
                    float tc[5] = {3e38f, 3e38f, 3e38f, 3e38f, 3e38f};
                    #pragma unroll
                    for (int a = 0; a < 4; a++) {
                        const int mb = a >> 1, h = a & 1;
                        const int gi = i0 + warp_m * 32 + mb * 16 + h * 8 + r;
                        float d2 = sqi[a] + sqj - 2.0f * acc[mb][nb][h * 2 + c];
                        d2 = fmaxf(d2, 0.0f);
                        if (gj != gi) { ins5(t5[a], d2); ins5(tc, d2); }
                        acc[mb][nb][h * 2 + c] = 0.f;
                    }
                    merge5_xor(tc, 4);
                    merge5_xor(tc, 8);
                    merge5_xor(tc, 16);
                    if (r == 0) {
                        #pragma unroll
                        for (int s = 0; s < 5; s++) colm[cl][warp_m * 5 + s] = tc[s];
                    }
                }

            #pragma unroll
            for (int a = 0; a < 4; a++) {
                merge5_xor(t5[a], 1);
                merge5_xor(t5[a], 2);
                if (qq == 0) {
                    const int rl = warp_m * 32 + (a >> 1) * 16 + (a & 1) * 8 + r;
                    #pragma unroll
                    for (int s = 0; s < 5; s++) rowm[rl][warp_n * 5 + s] = t5[a][s];
                }
                #pragma unroll
                for (int s = 0; s < 5; s++) t5[a][s] = 3.0e38f;
            }
            __syncthreads();

            if (tid < MT) {
                float t[5] = {3e38f, 3e38f, 3e38f, 3e38f, 3e38f};
                #pragma unroll
                for (int k = 0; k < 20; k++) ins5(t, rowm[tid][k]);
                #pragma unroll
                for (int s = 0; s < 5; s++) g_cand[bj][i0 + tid][s] = t[s];
            } else if (tid < 256 && bi != bj) {
                const int cl = tid - 128;
                float t[5] = {3e38f, 3e38f, 3e38f, 3e38f, 3e38f};
                #pragma unroll
                for (int k = 0; k < 20; k++) ins5(t, colm[cl][k]);
                #pragma unroll
                for (int s = 0; s < 5; s++) g_cand[bi][j0 + cl][s] = t[s];
            }
        }

        tile += GRID;
        bi = nBi; bj = nBj;
        curA = nxtA; curB = nxtB;
    }
}

// ---------------------------------------------------------------------------
// Kernel C: merge 64 candidate slots -> score -> weight -> scale into out[2,...]
// ---------------------------------------------------------------------------
__global__ __launch_bounds__(256) void finalize_kernel(const float* __restrict__ xr,
                                                       const float* __restrict__ xi,
                                                       float* __restrict__ out) {
    const int row = blockIdx.x;
    const int tid = threadIdx.x;
    __shared__ float buf[40];
    __shared__ float wsh;
    if (tid < 8) {
        float t[5] = {3e38f, 3e38f, 3e38f, 3e38f, 3e38f};
        #pragma unroll
        for (int s8 = 0; s8 < 8; s8++) {
            const int slot = tid * 8 + s8;
            #pragma unroll
            for (int s = 0; s < 5; s++) ins5(t, g_cand[slot][row][s]);
        }
        #pragma unroll
        for (int s = 0; s < 5; s++) buf[tid * 5 + s] = t[s];
    }
    __syncthreads();
    if (tid == 0) {
        float t[5] = {3e38f, 3e38f, 3e38f, 3e38f, 3e38f};
        #pragma unroll
        for (int k = 0; k < 40; k++) ins5(t, buf[k]);
        float sc = (sqrtf(t[0]) + sqrtf(t[1]) + sqrtf(t[2]) + sqrtf(t[3]) + sqrtf(t[4])) * 0.2f;
        wsh = (sc > 0.1f) ? expf(-sc * (1.0f / 32.0f)) : 0.0f;
    }
    __syncthreads();
    const float w = wsh;
    float4 a = reinterpret_cast<const float4*>(xr + (size_t)row * DDIM)[tid];
    float4 b = reinterpret_cast<const float4*>(xi + (size_t)row * DDIM)[tid];
    a.x *= w; a.y *= w; a.z *= w; a.w *= w;
    b.x *= w; b.y *= w; b.z *= w; b.w *= w;
    reinterpret_cast<float4*>(out + (size_t)row * DDIM)[tid] = a;
    reinterpret_cast<float4*>(out + ((size_t)NROWS + row) * DDIM)[tid] = b;
}

// ---------------------------------------------------------------------------
extern "C" void kernel_launch(void* const* d_in, const int* in_sizes, int n_in,
                              void* d_out, int out_size) {
    const float* xr = (const float*)d_in[0];
    const float* xi = (const float*)d_in[1];
    float* out = (float*)d_out;

    cudaFuncSetAttribute(gram_kernel, cudaFuncAttributeMaxDynamicSharedMemorySize, SMEM_DYN);

    prep_kernel<<<NROWS, 256>>>(xr);
    gram_kernel<<<GRID, 512, SMEM_DYN>>>();
    finalize_kernel<<<NROWS, 256>>>(xr, xi, out);
}